// round 1
// baseline (speedup 1.0000x reference)
#include <cuda_runtime.h>
#include <cuda_bf16.h>

#define NN 100000
#define NE 3200000
#define FIN 512
#define FH 256
#define FC 40

#define SCAN_B 1024
#define NSCANBLK ((NN + SCAN_B - 1) / SCAN_B)   // 98

// ---------------- scratch (device globals; no allocation allowed) -----------
__device__ __align__(16) float g_support[(size_t)NN * FH];  // X@W1
__device__ __align__(16) float g_h[(size_t)NN * FH];        // relu(A support + b1)
__device__ __align__(16) float g_z[(size_t)NN * FC];        // h@W2
__device__ int   g_cnt[NN];
__device__ int   g_rowptr[NN + 1];
__device__ int   g_cursor[NN];
__device__ int   g_bsum[NSCANBLK];
__device__ __align__(16) int   g_scol[NE];
__device__ __align__(16) float g_sval[NE];

// ---------------- CSR build --------------------------------------------------
__global__ void k_zero_cnt() {
    for (int i = blockIdx.x * blockDim.x + threadIdx.x; i < NN; i += gridDim.x * blockDim.x)
        g_cnt[i] = 0;
}

__global__ void k_hist(const int* __restrict__ erow) {
    for (int e = blockIdx.x * blockDim.x + threadIdx.x; e < NE; e += gridDim.x * blockDim.x)
        atomicAdd(&g_cnt[erow[e]], 1);
}

__global__ void k_scan1() {
    __shared__ int sh[SCAN_B];
    int b = blockIdx.x, t = threadIdx.x;
    int i = b * SCAN_B + t;
    int v = (i < NN) ? g_cnt[i] : 0;
    sh[t] = v;
    __syncthreads();
    for (int off = 1; off < SCAN_B; off <<= 1) {
        int x = (t >= off) ? sh[t - off] : 0;
        __syncthreads();
        sh[t] += x;
        __syncthreads();
    }
    if (i < NN) g_rowptr[i] = sh[t] - v;   // exclusive
    if (t == SCAN_B - 1) g_bsum[b] = sh[t];
}

__global__ void k_scan2() {
    if (threadIdx.x == 0) {
        int run = 0;
        for (int b = 0; b < NSCANBLK; b++) { int x = g_bsum[b]; g_bsum[b] = run; run += x; }
        g_rowptr[NN] = run;   // == NE
    }
}

__global__ void k_scan3() {
    for (int i = blockIdx.x * blockDim.x + threadIdx.x; i < NN; i += gridDim.x * blockDim.x) {
        int v = g_rowptr[i] + g_bsum[i >> 10];
        g_rowptr[i] = v;
        g_cursor[i] = v;
    }
}

__global__ void k_scatter(const float* __restrict__ eval,
                          const int* __restrict__ erow,
                          const int* __restrict__ ecol) {
    for (int e = blockIdx.x * blockDim.x + threadIdx.x; e < NE; e += gridDim.x * blockDim.x) {
        int r = erow[e];
        int p = atomicAdd(&g_cursor[r], 1);
        g_scol[p] = ecol[e];
        g_sval[p] = eval[e];
    }
}

// ---------------- GEMM1: support = X[NN,512] @ W1[512,256] -------------------
// BM=128, BN=64, BK=16, 256 threads, 8x4 per thread.
#define BM 128
#define BN 64
#define BK 16

__global__ __launch_bounds__(256) void k_gemm1(const float* __restrict__ x,
                                               const float* __restrict__ w1) {
    __shared__ float AsT[BK * BM];       // [k][m]
    __shared__ float Bs[BK * BN];        // [k][n]
    const int bn = blockIdx.x * BN;      // grid.x = 4 (N tiles) for L2 reuse of x
    const int bm = blockIdx.y * BM;
    const int tid = threadIdx.x;
    const int tr = tid >> 4;             // 0..15
    const int tc = tid & 15;             // 0..15

    float acc[8][4];
#pragma unroll
    for (int i = 0; i < 8; i++)
#pragma unroll
        for (int j = 0; j < 4; j++) acc[i][j] = 0.f;

    for (int k0 = 0; k0 < FIN; k0 += BK) {
        // load A tile (128x16) as float4, store transposed
#pragma unroll
        for (int v = tid; v < (BM * BK / 4); v += 256) {
            int r = v >> 2, c4 = v & 3;
            int gr = bm + r;
            float4 val = make_float4(0.f, 0.f, 0.f, 0.f);
            if (gr < NN)
                val = *reinterpret_cast<const float4*>(&x[(size_t)gr * FIN + k0 + c4 * 4]);
            AsT[(c4 * 4 + 0) * BM + r] = val.x;
            AsT[(c4 * 4 + 1) * BM + r] = val.y;
            AsT[(c4 * 4 + 2) * BM + r] = val.z;
            AsT[(c4 * 4 + 3) * BM + r] = val.w;
        }
        // load B tile (16x64)
        {
            int v = tid;                  // exactly 256 float4
            int r = v >> 4, c4 = v & 15;
            float4 val = *reinterpret_cast<const float4*>(&w1[(size_t)(k0 + r) * FH + bn + c4 * 4]);
            *reinterpret_cast<float4*>(&Bs[r * BN + c4 * 4]) = val;
        }
        __syncthreads();
#pragma unroll
        for (int kk = 0; kk < BK; kk++) {
            float a[8], b[4];
            float4 a0 = *reinterpret_cast<float4*>(&AsT[kk * BM + tr * 8]);
            float4 a1 = *reinterpret_cast<float4*>(&AsT[kk * BM + tr * 8 + 4]);
            a[0]=a0.x; a[1]=a0.y; a[2]=a0.z; a[3]=a0.w;
            a[4]=a1.x; a[5]=a1.y; a[6]=a1.z; a[7]=a1.w;
            float4 b0 = *reinterpret_cast<float4*>(&Bs[kk * BN + tc * 4]);
            b[0]=b0.x; b[1]=b0.y; b[2]=b0.z; b[3]=b0.w;
#pragma unroll
            for (int i = 0; i < 8; i++)
#pragma unroll
                for (int j = 0; j < 4; j++) acc[i][j] = fmaf(a[i], b[j], acc[i][j]);
        }
        __syncthreads();
    }
#pragma unroll
    for (int i = 0; i < 8; i++) {
        int gr = bm + tr * 8 + i;
        if (gr < NN) {
            float4 v = make_float4(acc[i][0], acc[i][1], acc[i][2], acc[i][3]);
            *reinterpret_cast<float4*>(&g_support[(size_t)gr * FH + bn + tc * 4]) = v;
        }
    }
}

// ---------------- SpMM1: h = relu(A @ support + b1) --------------------------
__global__ __launch_bounds__(256) void k_spmm1(const float* __restrict__ b1) {
    __shared__ int   shc[256];
    __shared__ float shv[256];
    const int r = blockIdx.x;
    const int t = threadIdx.x;
    const int s = g_rowptr[r], e = g_rowptr[r + 1];
    float acc = 0.f;
    for (int base = s; base < e; base += 256) {
        int idx = base + t;
        if (idx < e) { shc[t] = g_scol[idx]; shv[t] = g_sval[idx]; }
        __syncthreads();
        int m = min(256, e - base);
#pragma unroll 4
        for (int i = 0; i < m; i++)
            acc = fmaf(shv[i], g_support[(size_t)shc[i] * FH + t], acc);
        __syncthreads();
    }
    g_h[(size_t)r * FH + t] = fmaxf(acc + b1[t], 0.f);
}

// ---------------- GEMM2: z = h[NN,256] @ W2[256,40] --------------------------
#define G2_BM 64
#define G2_BK 64

__global__ __launch_bounds__(256) void k_gemm2(const float* __restrict__ w2) {
    __shared__ float shH[G2_BK * 65];   // [kk][row], pad 65 avoids bank conflicts
    __shared__ float shW[G2_BK * FC];   // [kk][c]
    const int rb = blockIdx.x * G2_BM;
    const int tid = threadIdx.x;
    const int row = tid >> 2;           // 0..63
    const int cg = tid & 3;             // 0..3
    float acc[10];
#pragma unroll
    for (int j = 0; j < 10; j++) acc[j] = 0.f;

    for (int k0 = 0; k0 < FH; k0 += G2_BK) {
#pragma unroll
        for (int v = tid; v < (G2_BM * G2_BK / 4); v += 256) {
            int r = v >> 4, c4 = v & 15;
            int gr = rb + r;
            float4 val = make_float4(0.f, 0.f, 0.f, 0.f);
            if (gr < NN)
                val = *reinterpret_cast<const float4*>(&g_h[(size_t)gr * FH + k0 + c4 * 4]);
            shH[(c4 * 4 + 0) * 65 + r] = val.x;
            shH[(c4 * 4 + 1) * 65 + r] = val.y;
            shH[(c4 * 4 + 2) * 65 + r] = val.z;
            shH[(c4 * 4 + 3) * 65 + r] = val.w;
        }
#pragma unroll
        for (int v = tid; v < G2_BK * FC; v += 256) {
            int r = v / FC, c = v % FC;
            shW[v] = w2[(size_t)(k0 + r) * FC + c];
        }
        __syncthreads();
#pragma unroll 8
        for (int kk = 0; kk < G2_BK; kk++) {
            float a = shH[kk * 65 + row];
#pragma unroll
            for (int j = 0; j < 10; j++)
                acc[j] = fmaf(a, shW[kk * FC + cg + 4 * j], acc[j]);
        }
        __syncthreads();
    }
    int gr = rb + row;
    if (gr < NN) {
#pragma unroll
        for (int j = 0; j < 10; j++)
            g_z[(size_t)gr * FC + cg + 4 * j] = acc[j];
    }
}

// ---------------- SpMM2 + bias + log_softmax ---------------------------------
__global__ __launch_bounds__(64) void k_spmm2(const float* __restrict__ b2,
                                              float* __restrict__ out) {
    __shared__ int   shc[64];
    __shared__ float shv[64];
    __shared__ float red[64];
    const int r = blockIdx.x;
    const int t = threadIdx.x;
    const int s = g_rowptr[r], e = g_rowptr[r + 1];
    float acc = 0.f;
    for (int base = s; base < e; base += 64) {
        int idx = base + t;
        if (idx < e) { shc[t] = g_scol[idx]; shv[t] = g_sval[idx]; }
        __syncthreads();
        int m = min(64, e - base);
        if (t < FC) {
#pragma unroll 4
            for (int i = 0; i < m; i++)
                acc = fmaf(shv[i], g_z[(size_t)shc[i] * FC + t], acc);
        }
        __syncthreads();
    }
    float val = (t < FC) ? (acc + b2[t]) : 0.f;
    red[t] = (t < FC) ? val : -3.4e38f;
    __syncthreads();
#pragma unroll
    for (int off = 32; off > 0; off >>= 1) {
        if (t < off) red[t] = fmaxf(red[t], red[t + off]);
        __syncthreads();
    }
    float mx = red[0];
    __syncthreads();
    red[t] = (t < FC) ? expf(val - mx) : 0.f;
    __syncthreads();
#pragma unroll
    for (int off = 32; off > 0; off >>= 1) {
        if (t < off) red[t] += red[t + off];
        __syncthreads();
    }
    float lse = mx + logf(red[0]);
    if (t < FC) out[(size_t)r * FC + t] = val - lse;
}

// ---------------- launch -----------------------------------------------------
extern "C" void kernel_launch(void* const* d_in, const int* in_sizes, int n_in,
                              void* d_out, int out_size) {
    const float* x    = (const float*)d_in[0];
    const float* w1   = (const float*)d_in[1];
    const float* b1   = (const float*)d_in[2];
    const float* w2   = (const float*)d_in[3];
    const float* b2   = (const float*)d_in[4];
    const float* eval = (const float*)d_in[5];
    const int*   erow = (const int*)d_in[6];
    const int*   ecol = (const int*)d_in[7];
    float* out = (float*)d_out;

    // CSR build
    k_zero_cnt<<<256, 256>>>();
    k_hist<<<2048, 256>>>(erow);
    k_scan1<<<NSCANBLK, SCAN_B>>>();
    k_scan2<<<1, 32>>>();
    k_scan3<<<196, 512>>>();
    k_scatter<<<2048, 256>>>(eval, erow, ecol);

    // layer 1
    dim3 g1(FH / BN, (NN + BM - 1) / BM);   // (4, 782): N tiles fast for x reuse in L2
    k_gemm1<<<g1, 256>>>(x, w1);
    k_spmm1<<<NN, 256>>>(b1);

    // layer 2 + log_softmax
    k_gemm2<<<(NN + G2_BM - 1) / G2_BM, 256>>>(w2);
    k_spmm2<<<NN, 64>>>(b2, out);
}

// round 2
// speedup vs baseline: 1.2501x; 1.2501x over previous
#include <cuda_runtime.h>
#include <cuda_bf16.h>

#define NN 100000
#define NE 3200000
#define FIN 512
#define FH 256
#define FC 40

#define SCAN_B 1024
#define NSCANBLK ((NN + SCAN_B - 1) / SCAN_B)   // 98

// ---------------- scratch (device globals; no allocation allowed) -----------
__device__ __align__(16) float g_support[(size_t)NN * FH];  // X@W1
__device__ __align__(16) float g_h[(size_t)NN * FH];        // relu(A support + b1)
__device__ __align__(16) float g_z[(size_t)NN * FC];        // h@W2
__device__ int   g_cnt[NN];
__device__ int   g_rowptr[NN + 1];
__device__ int   g_cursor[NN];
__device__ int   g_bsum[NSCANBLK];
__device__ __align__(16) int   g_scol[NE];
__device__ __align__(16) float g_sval[NE];

// ---------------- packed f32x2 helpers (Blackwell FFMA2) ---------------------
__device__ __forceinline__ unsigned long long pack2(float lo, float hi) {
    unsigned long long r;
    asm("mov.b64 %0,{%1,%2};" : "=l"(r) : "f"(lo), "f"(hi));
    return r;
}
__device__ __forceinline__ unsigned long long ffma2(unsigned long long a,
                                                    unsigned long long b,
                                                    unsigned long long c) {
    unsigned long long r;
    asm("fma.rn.f32x2 %0,%1,%2,%3;" : "=l"(r) : "l"(a), "l"(b), "l"(c));
    return r;
}
__device__ __forceinline__ float2 unpack2(unsigned long long v) {
    float2 f;
    asm("mov.b64 {%0,%1},%2;" : "=f"(f.x), "=f"(f.y) : "l"(v));
    return f;
}

// ---------------- CSR build --------------------------------------------------
__global__ void k_zero_cnt() {
    for (int i = blockIdx.x * blockDim.x + threadIdx.x; i < NN; i += gridDim.x * blockDim.x)
        g_cnt[i] = 0;
}

__global__ void k_hist(const int* __restrict__ erow) {
    for (int e = blockIdx.x * blockDim.x + threadIdx.x; e < NE; e += gridDim.x * blockDim.x)
        atomicAdd(&g_cnt[erow[e]], 1);
}

__global__ void k_scan1() {
    __shared__ int sh[SCAN_B];
    int b = blockIdx.x, t = threadIdx.x;
    int i = b * SCAN_B + t;
    int v = (i < NN) ? g_cnt[i] : 0;
    sh[t] = v;
    __syncthreads();
    for (int off = 1; off < SCAN_B; off <<= 1) {
        int x = (t >= off) ? sh[t - off] : 0;
        __syncthreads();
        sh[t] += x;
        __syncthreads();
    }
    if (i < NN) g_rowptr[i] = sh[t] - v;   // exclusive
    if (t == SCAN_B - 1) g_bsum[b] = sh[t];
}

__global__ void k_scan2() {
    if (threadIdx.x == 0) {
        int run = 0;
        for (int b = 0; b < NSCANBLK; b++) { int x = g_bsum[b]; g_bsum[b] = run; run += x; }
        g_rowptr[NN] = run;   // == NE
    }
}

__global__ void k_scan3() {
    for (int i = blockIdx.x * blockDim.x + threadIdx.x; i < NN; i += gridDim.x * blockDim.x) {
        int v = g_rowptr[i] + g_bsum[i >> 10];
        g_rowptr[i] = v;
        g_cursor[i] = v;
    }
}

__global__ void k_scatter(const float* __restrict__ eval,
                          const int* __restrict__ erow,
                          const int* __restrict__ ecol) {
    for (int e = blockIdx.x * blockDim.x + threadIdx.x; e < NE; e += gridDim.x * blockDim.x) {
        int r = erow[e];
        int p = atomicAdd(&g_cursor[r], 1);
        g_scol[p] = ecol[e];
        g_sval[p] = eval[e];
    }
}

// ---------------- GEMM1: support = X[NN,512] @ W1[512,256] -------------------
// f32x2 packed FFMA2. BM=128, BN=128, BK=16, 256 threads, 8x8 per thread
// (held as 8x4 packed-pair accumulators). Double-buffered smem.
#define BM 128
#define BN 128
#define BK 16
#define ASTR 132   // padded k-row stride for A^T tile: keeps float4 alignment, 2-way max conflict

__global__ __launch_bounds__(256, 2) void k_gemm1(const float* __restrict__ x,
                                                  const float* __restrict__ w1) {
    __shared__ float AsT[2][BK * ASTR];   // [k][m]
    __shared__ float Bs[2][BK * BN];      // [k][n]
    const int bn = blockIdx.x * BN;
    const int bm = blockIdx.y * BM;
    const int tid = threadIdx.x;
    const int tr = tid >> 4;              // 0..15 -> 8 rows each
    const int tc = tid & 15;              // 0..15 -> 8 cols each

    // A-load mapping: 512 float4 per tile, 2 per thread
    const int ar0 = tid >> 2, ac0 = tid & 3;        // row 0..63
    const int ar1 = ar0 + 64;                       // row 64..127, same c4
    // B-load mapping: 512 float4 per tile, 2 per thread
    const int br0 = tid >> 5, bc0 = tid & 31;       // row 0..7
    const int br1 = br0 + 8;                        // row 8..15

    unsigned long long acc[8][4];
#pragma unroll
    for (int i = 0; i < 8; i++)
#pragma unroll
        for (int j = 0; j < 4; j++) acc[i][j] = 0ULL;

    const float4 z4 = make_float4(0.f, 0.f, 0.f, 0.f);

    // preload tile k0=0
    {
        int gr0 = bm + ar0, gr1 = bm + ar1;
        float4 va0 = (gr0 < NN) ? *(const float4*)&x[(size_t)gr0 * FIN + ac0 * 4] : z4;
        float4 va1 = (gr1 < NN) ? *(const float4*)&x[(size_t)gr1 * FIN + ac0 * 4] : z4;
        float4 vb0 = *(const float4*)&w1[(size_t)br0 * FH + bn + bc0 * 4];
        float4 vb1 = *(const float4*)&w1[(size_t)br1 * FH + bn + bc0 * 4];
        AsT[0][(ac0 * 4 + 0) * ASTR + ar0] = va0.x;
        AsT[0][(ac0 * 4 + 1) * ASTR + ar0] = va0.y;
        AsT[0][(ac0 * 4 + 2) * ASTR + ar0] = va0.z;
        AsT[0][(ac0 * 4 + 3) * ASTR + ar0] = va0.w;
        AsT[0][(ac0 * 4 + 0) * ASTR + ar1] = va1.x;
        AsT[0][(ac0 * 4 + 1) * ASTR + ar1] = va1.y;
        AsT[0][(ac0 * 4 + 2) * ASTR + ar1] = va1.z;
        AsT[0][(ac0 * 4 + 3) * ASTR + ar1] = va1.w;
        *(float4*)&Bs[0][br0 * BN + bc0 * 4] = vb0;
        *(float4*)&Bs[0][br1 * BN + bc0 * 4] = vb1;
    }
    __syncthreads();

    int buf = 0;
    for (int k0 = 0; k0 < FIN; k0 += BK) {
        const bool last = (k0 + BK >= FIN);
        float4 va0, va1, vb0, vb1;
        if (!last) {
            int kn = k0 + BK;
            int gr0 = bm + ar0, gr1 = bm + ar1;
            va0 = (gr0 < NN) ? *(const float4*)&x[(size_t)gr0 * FIN + kn + ac0 * 4] : z4;
            va1 = (gr1 < NN) ? *(const float4*)&x[(size_t)gr1 * FIN + kn + ac0 * 4] : z4;
            vb0 = *(const float4*)&w1[(size_t)(kn + br0) * FH + bn + bc0 * 4];
            vb1 = *(const float4*)&w1[(size_t)(kn + br1) * FH + bn + bc0 * 4];
        }
#pragma unroll
        for (int kk = 0; kk < BK; kk++) {
            float4 a0 = *(const float4*)&AsT[buf][kk * ASTR + tr * 8];
            float4 a1 = *(const float4*)&AsT[buf][kk * ASTR + tr * 8 + 4];
            ulonglong2 bb0 = *(const ulonglong2*)&Bs[buf][kk * BN + tc * 8];
            ulonglong2 bb1 = *(const ulonglong2*)&Bs[buf][kk * BN + tc * 8 + 4];
            unsigned long long bp[4] = {bb0.x, bb0.y, bb1.x, bb1.y};
            float av[8] = {a0.x, a0.y, a0.z, a0.w, a1.x, a1.y, a1.z, a1.w};
#pragma unroll
            for (int i = 0; i < 8; i++) {
                unsigned long long a2 = pack2(av[i], av[i]);
#pragma unroll
                for (int j = 0; j < 4; j++)
                    acc[i][j] = ffma2(a2, bp[j], acc[i][j]);
            }
        }
        if (!last) {
            int nb = buf ^ 1;
            AsT[nb][(ac0 * 4 + 0) * ASTR + ar0] = va0.x;
            AsT[nb][(ac0 * 4 + 1) * ASTR + ar0] = va0.y;
            AsT[nb][(ac0 * 4 + 2) * ASTR + ar0] = va0.z;
            AsT[nb][(ac0 * 4 + 3) * ASTR + ar0] = va0.w;
            AsT[nb][(ac0 * 4 + 0) * ASTR + ar1] = va1.x;
            AsT[nb][(ac0 * 4 + 1) * ASTR + ar1] = va1.y;
            AsT[nb][(ac0 * 4 + 2) * ASTR + ar1] = va1.z;
            AsT[nb][(ac0 * 4 + 3) * ASTR + ar1] = va1.w;
            *(float4*)&Bs[nb][br0 * BN + bc0 * 4] = vb0;
            *(float4*)&Bs[nb][br1 * BN + bc0 * 4] = vb1;
        }
        __syncthreads();
        buf ^= 1;
    }

#pragma unroll
    for (int i = 0; i < 8; i++) {
        int gr = bm + tr * 8 + i;
        if (gr < NN) {
            float2 c0 = unpack2(acc[i][0]), c1 = unpack2(acc[i][1]);
            float2 c2 = unpack2(acc[i][2]), c3 = unpack2(acc[i][3]);
            *(float4*)&g_support[(size_t)gr * FH + bn + tc * 8] =
                make_float4(c0.x, c0.y, c1.x, c1.y);
            *(float4*)&g_support[(size_t)gr * FH + bn + tc * 8 + 4] =
                make_float4(c2.x, c2.y, c3.x, c3.y);
        }
    }
}

// ---------------- SpMM1: h = relu(A @ support + b1) --------------------------
// 128 threads, 2 features (one f32x2 pair) per thread.
__global__ __launch_bounds__(128) void k_spmm1(const float* __restrict__ b1) {
    __shared__ int   shc[128];
    __shared__ float shv[128];
    const int r = blockIdx.x;
    const int t = threadIdx.x;
    const int s = g_rowptr[r], e = g_rowptr[r + 1];
    unsigned long long acc = 0ULL;
    for (int base = s; base < e; base += 128) {
        int idx = base + t;
        if (idx < e) { shc[t] = g_scol[idx]; shv[t] = g_sval[idx]; }
        __syncthreads();
        int m = min(128, e - base);
#pragma unroll 4
        for (int i = 0; i < m; i++) {
            unsigned long long v =
                *(const unsigned long long*)&g_support[(size_t)shc[i] * FH + 2 * t];
            acc = ffma2(pack2(shv[i], shv[i]), v, acc);
        }
        __syncthreads();
    }
    float2 a = unpack2(acc);
    float2 bb = *(const float2*)&b1[2 * t];
    float2 o = make_float2(fmaxf(a.x + bb.x, 0.f), fmaxf(a.y + bb.y, 0.f));
    *(float2*)&g_h[(size_t)r * FH + 2 * t] = o;
}

// ---------------- GEMM2: z = h[NN,256] @ W2[256,40] --------------------------
// 256 threads, one node-row per thread, 40 outputs = 20 packed pairs.
#define Z_BK 32
#define HSTR 258

__global__ __launch_bounds__(256, 2) void k_gemm2(const float* __restrict__ w2) {
    __shared__ float shH[Z_BK * HSTR];   // [kk][row], padded stride
    __shared__ float shW[Z_BK * FC];     // [kk][c]
    const int rb = blockIdx.x * 256;
    const int tid = threadIdx.x;
    const int row = rb + tid;

    unsigned long long acc[20];
#pragma unroll
    for (int j = 0; j < 20; j++) acc[j] = 0ULL;

    const float4 z4 = make_float4(0.f, 0.f, 0.f, 0.f);

    for (int k0 = 0; k0 < FH; k0 += Z_BK) {
        // h tile: 256 rows x 32 k = 2048 float4, 8 per thread, store transposed
#pragma unroll
        for (int q = 0; q < 8; q++) {
            int L = tid + q * 256;
            int lr = L >> 3, c4 = L & 7;
            int gr = rb + lr;
            float4 v = (gr < NN) ? *(const float4*)&g_h[(size_t)gr * FH + k0 + c4 * 4] : z4;
            shH[(c4 * 4 + 0) * HSTR + lr] = v.x;
            shH[(c4 * 4 + 1) * HSTR + lr] = v.y;
            shH[(c4 * 4 + 2) * HSTR + lr] = v.z;
            shH[(c4 * 4 + 3) * HSTR + lr] = v.w;
        }
        // w2 tile: 32x40 = 320 float4-loads worth (1280 floats = 320 float4)
        {
            int L = tid;
            if (L < 320) {
                int rr = L / 10, c4 = L % 10;
                *(float4*)&shW[rr * FC + c4 * 4] =
                    *(const float4*)&w2[(size_t)(k0 + rr) * FC + c4 * 4];
            }
            L = tid + 256;
            if (L < 320) {
                int rr = L / 10, c4 = L % 10;
                *(float4*)&shW[rr * FC + c4 * 4] =
                    *(const float4*)&w2[(size_t)(k0 + rr) * FC + c4 * 4];
            }
        }
        __syncthreads();
#pragma unroll
        for (int kk = 0; kk < Z_BK; kk++) {
            float a = shH[kk * HSTR + tid];
            unsigned long long a2 = pack2(a, a);
#pragma unroll
            for (int p = 0; p < 10; p++) {
                ulonglong2 bb = *(const ulonglong2*)&shW[kk * FC + p * 4];
                acc[2 * p]     = ffma2(a2, bb.x, acc[2 * p]);
                acc[2 * p + 1] = ffma2(a2, bb.y, acc[2 * p + 1]);
            }
        }
        __syncthreads();
    }
    if (row < NN) {
#pragma unroll
        for (int p = 0; p < 10; p++) {
            float2 c0 = unpack2(acc[2 * p]), c1 = unpack2(acc[2 * p + 1]);
            *(float4*)&g_z[(size_t)row * FC + p * 4] = make_float4(c0.x, c0.y, c1.x, c1.y);
        }
    }
}

// ---------------- SpMM2 + bias + log_softmax ---------------------------------
__global__ __launch_bounds__(64) void k_spmm2(const float* __restrict__ b2,
                                              float* __restrict__ out) {
    __shared__ int   shc[64];
    __shared__ float shv[64];
    __shared__ float red[64];
    const int r = blockIdx.x;
    const int t = threadIdx.x;
    const int s = g_rowptr[r], e = g_rowptr[r + 1];
    float acc = 0.f;
    for (int base = s; base < e; base += 64) {
        int idx = base + t;
        if (idx < e) { shc[t] = g_scol[idx]; shv[t] = g_sval[idx]; }
        __syncthreads();
        int m = min(64, e - base);
        if (t < FC) {
#pragma unroll 4
            for (int i = 0; i < m; i++)
                acc = fmaf(shv[i], g_z[(size_t)shc[i] * FC + t], acc);
        }
        __syncthreads();
    }
    float val = (t < FC) ? (acc + b2[t]) : 0.f;
    red[t] = (t < FC) ? val : -3.4e38f;
    __syncthreads();
#pragma unroll
    for (int off = 32; off > 0; off >>= 1) {
        if (t < off) red[t] = fmaxf(red[t], red[t + off]);
        __syncthreads();
    }
    float mx = red[0];
    __syncthreads();
    red[t] = (t < FC) ? expf(val - mx) : 0.f;
    __syncthreads();
#pragma unroll
    for (int off = 32; off > 0; off >>= 1) {
        if (t < off) red[t] += red[t + off];
        __syncthreads();
    }
    float lse = mx + logf(red[0]);
    if (t < FC) out[(size_t)r * FC + t] = val - lse;
}

// ---------------- launch -----------------------------------------------------
extern "C" void kernel_launch(void* const* d_in, const int* in_sizes, int n_in,
                              void* d_out, int out_size) {
    const float* x    = (const float*)d_in[0];
    const float* w1   = (const float*)d_in[1];
    const float* b1   = (const float*)d_in[2];
    const float* w2   = (const float*)d_in[3];
    const float* b2   = (const float*)d_in[4];
    const float* eval = (const float*)d_in[5];
    const int*   erow = (const int*)d_in[6];
    const int*   ecol = (const int*)d_in[7];
    float* out = (float*)d_out;

    // CSR build
    k_zero_cnt<<<256, 256>>>();
    k_hist<<<2048, 256>>>(erow);
    k_scan1<<<NSCANBLK, SCAN_B>>>();
    k_scan2<<<1, 32>>>();
    k_scan3<<<196, 512>>>();
    k_scatter<<<2048, 256>>>(eval, erow, ecol);

    // layer 1
    dim3 g1(FH / BN, (NN + BM - 1) / BM);   // (2, 782)
    k_gemm1<<<g1, 256>>>(x, w1);
    k_spmm1<<<NN, 128>>>(b1);

    // layer 2 + log_softmax
    k_gemm2<<<(NN + 255) / 256, 256>>>(w2);
    k_spmm2<<<NN, 64>>>(b2, out);
}